// round 11
// baseline (speedup 1.0000x reference)
#include <cuda_runtime.h>
#include <cuda_fp16.h>
#include <cstdint>
#include <cstddef>

#define T_STEPS 2048
#define N_ENV   256
#define HID     128
#define G3      384
#define IDIM    128
#define M_TOTAL (T_STEPS*N_ENV)
#define LDA     132
#define EPC     8            // envs per CTA (k2)
#define NCTA2   (N_ENV/EPC)  // 32 CTAs

// Scratch for gi = x @ w_ih^T + b_ih : [M_TOTAL, G3] fp32 (805 MB)
__device__ float g_gi[(size_t)M_TOTAL * G3];

// ---------------------------------------------------------------------------
// helpers (sm_103 base target — NO tcgen05)
// ---------------------------------------------------------------------------
__device__ __forceinline__ unsigned f2tf(float f){
  unsigned u; asm("cvt.rna.tf32.f32 %0, %1;" : "=r"(u) : "f"(f)); return u;
}
__device__ __forceinline__ void mma8(float* c, const unsigned* a, const unsigned* b){
  asm volatile("mma.sync.aligned.m16n8k8.row.col.f32.tf32.tf32.f32 "
      "{%0,%1,%2,%3}, {%4,%5,%6,%7}, {%8,%9}, {%0,%1,%2,%3};"
      : "+f"(c[0]), "+f"(c[1]), "+f"(c[2]), "+f"(c[3])
      : "r"(a[0]), "r"(a[1]), "r"(a[2]), "r"(a[3]), "r"(b[0]), "r"(b[1]));
}
__device__ __forceinline__ void hmma16(float* c, const unsigned* a, unsigned b0, unsigned b1){
  asm volatile("mma.sync.aligned.m16n8k16.row.col.f32.f16.f16.f32 "
      "{%0,%1,%2,%3}, {%4,%5,%6,%7}, {%8,%9}, {%0,%1,%2,%3};"
      : "+f"(c[0]), "+f"(c[1]), "+f"(c[2]), "+f"(c[3])
      : "r"(a[0]), "r"(a[1]), "r"(a[2]), "r"(a[3]), "r"(b0), "r"(b1));
}
__device__ __forceinline__ void ldsm4(unsigned* r, unsigned addr){
  asm volatile("ldmatrix.sync.aligned.m8n8.x4.shared.b16 {%0,%1,%2,%3}, [%4];"
      : "=r"(r[0]), "=r"(r[1]), "=r"(r[2]), "=r"(r[3]) : "r"(addr));
}
__device__ __forceinline__ unsigned lds32(unsigned a){
  unsigned v; asm volatile("ld.shared.b32 %0, [%1];" : "=r"(v) : "r"(a)); return v;
}
__device__ __forceinline__ void cp16(void* dst, const void* src){
  unsigned s = (unsigned)__cvta_generic_to_shared(dst);
  asm volatile("cp.async.cg.shared.global [%0], [%1], 16;" :: "r"(s), "l"(src));
}
__device__ __forceinline__ unsigned smem_u32(const void* p){
  return (unsigned)__cvta_generic_to_shared(p);
}
__device__ __forceinline__ unsigned pkh2(float a, float b){
  __half2 h = __floats2half2_rn(a, b);
  unsigned u; memcpy(&u, &h, 4); return u;
}
__device__ __forceinline__ float sigf(float x){
  return __fdividef(1.0f, 1.0f + __expf(-x));
}
__device__ __forceinline__ float tanhf_(float x){
  return __fdividef(2.0f, 1.0f + __expf(-2.0f*x)) - 1.0f;
}

// ---------------------------------------------------------------------------
// K1: gi = x @ w_ih^T + b_ih   (tf32 mma.sync) — exact R5 version (passing)
// ---------------------------------------------------------------------------
__global__ void __launch_bounds__(256) k1_gi(const float* __restrict__ x,
                                             const float* __restrict__ w_ih,
                                             const float* __restrict__ b_ih){
  extern __shared__ float sm[];
  float* Bs   = sm;
  float* As   = sm + 128*LDA;
  float* bias = sm + 3*128*LDA;

  const int tid  = threadIdx.x;
  const int nb   = blockIdx.x;
  const int slab = blockIdx.y;
  const int gbase = nb * 128;

  for (int idx = tid; idx < 128*32; idx += 256){
    int r = idx >> 5, c4 = idx & 31;
    float4 v = reinterpret_cast<const float4*>(w_ih + (size_t)(gbase + r)*IDIM)[c4];
    float* d = Bs + r*LDA + c4*4;
    d[0] = __uint_as_float(f2tf(v.x));
    d[1] = __uint_as_float(f2tf(v.y));
    d[2] = __uint_as_float(f2tf(v.z));
    d[3] = __uint_as_float(f2tf(v.w));
  }
  if (tid < 128) bias[tid] = b_ih[gbase + tid];

  const int lane = tid & 31, wid = tid >> 5;
  const int wm = wid >> 1, wn = wid & 1;
  const int grp = lane >> 2, qid = lane & 3;

  {
    const float* srcb = x + (size_t)slab * 128 * IDIM;
    #pragma unroll
    for (int i = 0; i < 16; i++){
      int c = tid + 256*i;
      int r = c >> 5, c16 = c & 31;
      cp16(As + r*LDA + c16*4, srcb + (size_t)r*IDIM + c16*4);
    }
    asm volatile("cp.async.commit_group;");
  }

  for (int it = 0; it < 32; it++){
    const int buf = it & 1;
    if (it + 1 < 32){
      int mt = slab + (it+1)*128;
      const float* srcb = x + (size_t)mt * 128 * IDIM;
      float* dstb = As + ((it+1)&1)*128*LDA;
      #pragma unroll
      for (int i = 0; i < 16; i++){
        int c = tid + 256*i;
        int r = c >> 5, c16 = c & 31;
        cp16(dstb + r*LDA + c16*4, srcb + (size_t)r*IDIM + c16*4);
      }
      asm volatile("cp.async.commit_group;");
      asm volatile("cp.async.wait_group 1;");
    } else {
      asm volatile("cp.async.wait_group 0;");
    }
    __syncthreads();

    float c[2][8][4];
    #pragma unroll
    for (int am=0;am<2;am++)
      #pragma unroll
      for(int an=0;an<8;an++)
        #pragma unroll
        for(int k=0;k<4;k++) c[am][an][k]=0.f;

    const float* A = As + buf*128*LDA;
    for (int k0 = 0; k0 < 128; k0 += 8){
      unsigned af[2][4];
      #pragma unroll
      for (int am=0; am<2; am++){
        int r0 = wm*32 + am*16 + grp;
        af[am][0] = f2tf(A[r0*LDA + k0 + qid]);
        af[am][1] = f2tf(A[(r0+8)*LDA + k0 + qid]);
        af[am][2] = f2tf(A[r0*LDA + k0 + qid + 4]);
        af[am][3] = f2tf(A[(r0+8)*LDA + k0 + qid + 4]);
      }
      unsigned bf[8][2];
      #pragma unroll
      for (int an=0; an<8; an++){
        int nr = wn*64 + an*8 + grp;
        bf[an][0] = __float_as_uint(Bs[nr*LDA + k0 + qid]);
        bf[an][1] = __float_as_uint(Bs[nr*LDA + k0 + qid + 4]);
      }
      #pragma unroll
      for (int am=0; am<2; am++)
        #pragma unroll
        for (int an=0; an<8; an++)
          mma8(c[am][an], af[am], bf[an]);
    }
    __syncthreads();

    const int mrow = (slab + it*128) * 128;
    #pragma unroll
    for (int am=0; am<2; am++){
      int r0 = mrow + wm*32 + am*16 + grp;
      #pragma unroll
      for (int an=0; an<8; an++){
        int colL = wn*64 + an*8 + 2*qid;
        float b0 = bias[colL], b1 = bias[colL+1];
        float2 v0 = make_float2(c[am][an][0]+b0, c[am][an][1]+b1);
        float2 v1 = make_float2(c[am][an][2]+b0, c[am][an][3]+b1);
        *reinterpret_cast<float2*>(&g_gi[(size_t)r0*G3 + gbase + colL]) = v0;
        *reinterpret_cast<float2*>(&g_gi[(size_t)(r0+8)*G3 + gbase + colL]) = v1;
      }
    }
  }
}

// ---------------------------------------------------------------------------
// K2: HMMA GRU scan. 32 CTAs x 384 threads, 8 envs per CTA.
// gh[384x8] = W@h via m16n8k16 fp16 mma.sync with split precision:
//   W = Whi(regs) + Wlo(smem, ldmatrix);  h = hhi + hlo (fp16 smem)
//   acc(fp32) += Whi*hhi + Whi*hlo + Wlo*hhi   (Wlo*hlo ~ 2e-6, dropped)
// Warp w owns rows 32w..32w+31 (2 M-tiles); accumulators stay in registers,
// then STS to gh smem; all 384 threads run gates for 1024 (j,env) units.
// gi/masks staged via cp.async ring (2-step lookahead, proven pattern).
// ---------------------------------------------------------------------------
// smem layout (bytes)
#define WLO_OFF 0          // Wlo fp16 [384][136]  (104448)
#define HHI_OFF 104448     // hhi fp16 [8][136]    (2176)
#define HLO_OFF 106624     // hlo fp16 [8][136]    (2176)
#define GH_OFF  108800     // gh fp32 [8][388]     (12416)
#define GI_OFF  121216     // gi ring [4][8][384]  (49152)
#define HS_OFF  170368     // h fp32 [8][128]      (4096)
#define MK_OFF  174464     // mask ring [4][8]     (128)
#define BI_OFF  174592     // b_hh [384]           (1536)
#define K2_SMEM 176128

__global__ void __launch_bounds__(384, 1) k2_scan(
    const float* __restrict__ h0,
    const float* __restrict__ masks,
    const float* __restrict__ w_hh,
    const float* __restrict__ b_hh,
    float* __restrict__ outs,
    float* __restrict__ h_final)
{
  extern __shared__ __align__(1024) char SM[];
  __half* wloS = (__half*)(SM + WLO_OFF);
  __half* hhiS = (__half*)(SM + HHI_OFF);
  __half* hloS = (__half*)(SM + HLO_OFF);
  float*  ghS  = (float*)(SM + GH_OFF);
  float*  giS  = (float*)(SM + GI_OFF);
  float*  hS   = (float*)(SM + HS_OFF);
  float*  mS   = (float*)(SM + MK_OFF);
  float*  bS   = (float*)(SM + BI_OFF);

  const int g    = threadIdx.x;
  const int wid  = g >> 5;
  const int lane = g & 31;
  const int grp  = lane >> 2;       // fragment group (env col / row base)
  const int qid  = lane & 3;
  const int e0   = blockIdx.x * EPC;
  const int m0w  = wid * 32;        // this warp's row base
  const size_t OUT_STRIDE = (size_t)N_ENV*HID;

  // ---- Whi fragments in registers: [2 tiles][8 ksteps][4 b32] = 64 regs ----
  unsigned whi[2][8][4];
  #pragma unroll
  for (int mt = 0; mt < 2; mt++){
    #pragma unroll
    for (int kd = 0; kd < 8; kd++){
      int r0 = m0w + mt*16 + grp;
      int c0 = kd*16 + qid*2;
      const float* w0 = w_hh + (size_t)r0*HID + c0;
      const float* w1 = w_hh + (size_t)(r0+8)*HID + c0;
      whi[mt][kd][0] = pkh2(w0[0], w0[1]);
      whi[mt][kd][1] = pkh2(w1[0], w1[1]);
      whi[mt][kd][2] = pkh2(w0[8], w0[9]);
      whi[mt][kd][3] = pkh2(w1[8], w1[9]);
    }
  }
  // ---- Wlo = W - fp16(W) into smem (padded rows of 136) ----
  for (int idx = g; idx < G3*HID; idx += 384){
    int r = idx >> 7, c = idx & 127;
    float wv = w_hh[idx];
    float hi = __half2float(__float2half_rn(wv));
    wloS[r*136 + c] = __float2half_rn(wv - hi);
  }
  // ---- h0: fp32 master + hi/lo fp16 split ----
  for (int idx = g; idx < EPC*HID; idx += 384){
    int e = idx >> 7, j = idx & 127;
    float hv = h0[(size_t)(e0+e)*HID + j];
    hS[idx] = hv;
    __half hh = __float2half_rn(hv);
    hhiS[e*136 + j] = hh;
    hloS[e*136 + j] = __float2half_rn(hv - __half2float(hh));
  }
  bS[g] = b_hh[g];

  // ---- gi/mask ring prologue: steps 0 and 1 ----
  #pragma unroll
  for (int pt = 0; pt < 2; pt++){
    const float* src = g_gi + ((size_t)pt*N_ENV + e0)*G3;
    cp16(giS + pt*(EPC*G3) + 4*g,            src + 4*g);
    cp16(giS + pt*(EPC*G3) + 1536 + 4*g,     src + 1536 + 4*g);
    if (g < 2) cp16(mS + pt*EPC + 4*g, masks + (size_t)pt*N_ENV + e0 + 4*g);
    asm volatile("cp.async.commit_group;");
  }
  __syncthreads();

  // ---- precomputed per-lane smem addresses ----
  const unsigned lmrow = (lane & 7) + ((lane >> 3) & 1) * 8;
  const unsigned lmcol = ((lane >> 4) & 1) * 8;
  const unsigned lmb0 = smem_u32(wloS) + ((m0w      + lmrow)*136 + lmcol)*2;
  const unsigned lmb1 = smem_u32(wloS) + ((m0w + 16 + lmrow)*136 + lmcol)*2;
  const unsigned hhib = smem_u32(hhiS) + (grp*136 + qid*2)*2;
  const unsigned hlob = smem_u32(hloS) + (grp*136 + qid*2)*2;

  #pragma unroll 1
  for (int t = 0; t < T_STEPS; t++){
    // stage step t+2 into ring slot (t+2)&3
    if (t + 2 < T_STEPS){
      const int sl2 = (t+2) & 3;
      const float* src = g_gi + ((size_t)(t+2)*N_ENV + e0)*G3;
      cp16(giS + sl2*(EPC*G3) + 4*g,        src + 4*g);
      cp16(giS + sl2*(EPC*G3) + 1536 + 4*g, src + 1536 + 4*g);
      if (g < 2) cp16(mS + sl2*EPC + 4*g, masks + (size_t)(t+2)*N_ENV + e0 + 4*g);
    }
    asm volatile("cp.async.commit_group;");
    asm volatile("cp.async.wait_group 2;");

    // ---- matvec: gh rows [m0w, m0w+32), 3-product split accumulation ----
    float c0[4] = {0.f,0.f,0.f,0.f};
    float c1[4] = {0.f,0.f,0.f,0.f};
    #pragma unroll
    for (int kd = 0; kd < 8; kd++){
      unsigned bh0 = lds32(hhib + kd*32);
      unsigned bh1 = lds32(hhib + kd*32 + 16);
      unsigned bl0 = lds32(hlob + kd*32);
      unsigned bl1 = lds32(hlob + kd*32 + 16);
      unsigned wl0[4], wl1[4];
      ldsm4(wl0, lmb0 + kd*32);
      ldsm4(wl1, lmb1 + kd*32);
      hmma16(c0, whi[0][kd], bh0, bh1);
      hmma16(c0, whi[0][kd], bl0, bl1);
      hmma16(c0, wl0,        bh0, bh1);
      hmma16(c1, whi[1][kd], bh0, bh1);
      hmma16(c1, whi[1][kd], bl0, bl1);
      hmma16(c1, wl1,        bh0, bh1);
    }
    // STS gh: C layout -> gh[env][row] (row stride 388 => conflict-free)
    {
      int r0 = m0w + grp;
      ghS[(2*qid  )*388 + r0    ] = c0[0];
      ghS[(2*qid+1)*388 + r0    ] = c0[1];
      ghS[(2*qid  )*388 + r0 + 8] = c0[2];
      ghS[(2*qid+1)*388 + r0 + 8] = c0[3];
      ghS[(2*qid  )*388 + r0 +16] = c1[0];
      ghS[(2*qid+1)*388 + r0 +16] = c1[1];
      ghS[(2*qid  )*388 + r0 +24] = c1[2];
      ghS[(2*qid+1)*388 + r0 +24] = c1[3];
    }
    __syncthreads();

    // ---- gates: 1024 (j,e) units over 384 threads ----
    {
      const int sl = t & 3;
      const float* giSL = giS + sl*(EPC*G3);
      #pragma unroll
      for (int u = 0; u < 3; u++){
        int idx = g + 384*u;
        if (u < 2 || idx < EPC*HID){
          int j = idx & 127, e = idx >> 7;
          float m  = mS[sl*EPC + e];
          const float* gie = giSL + e*G3;
          float cr = gie[j], cz = gie[128+j], cn = gie[256+j];
          const float* ghe = ghS + e*388;
          float sr = ghe[j], sz = ghe[128+j], sn = ghe[256+j];
          float hold = hS[idx];
          float r = sigf(cr + fmaf(m, sr, bS[j]));
          float z = sigf(cz + fmaf(m, sz, bS[128+j]));
          float n = tanhf_(cn + r * fmaf(m, sn, bS[256+j]));
          float hn = fmaf(z, fmaf(m, hold, -n), n);
          hS[idx] = hn;
          __half hh = __float2half_rn(hn);
          hhiS[e*136 + j] = hh;
          hloS[e*136 + j] = __float2half_rn(hn - __half2float(hh));
          outs[(size_t)t*OUT_STRIDE + (size_t)(e0+e)*HID + j] = hn;
          if (t == T_STEPS-1 && h_final != nullptr)
            h_final[(size_t)(e0+e)*HID + j] = hn;
        }
      }
    }
    __syncthreads();
  }
}

// ---------------------------------------------------------------------------
extern "C" void kernel_launch(void* const* d_in, const int* in_sizes, int n_in,
                              void* d_out, int out_size){
  (void)in_sizes; (void)n_in;
  const float* x     = (const float*)d_in[0];
  const float* h0    = (const float*)d_in[1];
  const float* masks = (const float*)d_in[2];
  const float* w_ih  = (const float*)d_in[3];
  const float* w_hh  = (const float*)d_in[4];
  const float* b_ih  = (const float*)d_in[5];
  const float* b_hh  = (const float*)d_in[6];

  float* outs = (float*)d_out;
  float* hf = nullptr;
  if ((long long)out_size >= (long long)M_TOTAL*HID + (long long)N_ENV*HID)
    hf = outs + (size_t)M_TOTAL*HID;

  const int k1_smem = (3*128*LDA + 128) * (int)sizeof(float);
  cudaFuncSetAttribute(k1_gi, cudaFuncAttributeMaxDynamicSharedMemorySize, k1_smem);
  k1_gi<<<dim3(3,128), 256, k1_smem>>>(x, w_ih, b_ih);

  cudaFuncSetAttribute(k2_scan, cudaFuncAttributeMaxDynamicSharedMemorySize, K2_SMEM);
  k2_scan<<<NCTA2, 384, K2_SMEM>>>(h0, masks, w_hh, b_hh, outs, hf);
}